// round 7
// baseline (speedup 1.0000x reference)
#include <cuda_runtime.h>
#include <cstdint>

#define FULL 0xffffffffu

static constexpr int S = 8;
static constexpr int N = 4096;
static constexpr int M = 64;
static constexpr int SN = S * N;

__device__ float  g_v8[32];      // v8[tt][8] = td_table[tt] @ en1_w
__device__ float4 g_pos4[SN];    // (x, y, z, type)

// ---------------------------------------------------------------------------
// Prepass: pack positions+type into float4 (4 atoms/thread, vectorized);
// block 0 collapses species MLPs into the v8 table.
// ---------------------------------------------------------------------------
__global__ void pack_kernel(
    const float* __restrict__ pos, const int* __restrict__ types,
    const float* __restrict__ es1_w, const float* __restrict__ es1_b,
    const float* __restrict__ es2_w, const float* __restrict__ es2_b,
    const float* __restrict__ fs1_w, const float* __restrict__ fs1_b,
    const float* __restrict__ fs2_w, const float* __restrict__ fs2_b,
    const float* __restrict__ en1_w)
{
    const int idx = blockIdx.x * blockDim.x + threadIdx.x;
    if (idx < SN / 4) {
        const float4* pv = reinterpret_cast<const float4*>(pos) + idx * 3;
        const float4 a = pv[0], b = pv[1], c = pv[2];
        const int4 t = reinterpret_cast<const int4*>(types)[idx];
        float4* o = g_pos4 + idx * 4;
        o[0] = make_float4(a.x, a.y, a.z, (float)t.x);
        o[1] = make_float4(a.w, b.x, b.y, (float)t.y);
        o[2] = make_float4(b.z, b.w, c.x, (float)t.z);
        o[3] = make_float4(c.y, c.z, c.w, (float)t.w);
    }

    if (blockIdx.x == 0 && threadIdx.x < 4) {
        const int tt = threadIdx.x;
        const float ti = (float)(tt >> 1);
        const float tj = (float)(tt & 1);

        float e[4];
        {
            float h[4];
            #pragma unroll
            for (int k = 0; k < 4; k++)
                h[k] = fmaxf(ti * es1_w[k] + tj * es1_w[4 + k] + es1_b[k], 0.f);
            #pragma unroll
            for (int k = 0; k < 4; k++) {
                float aa = es2_b[k];
                #pragma unroll
                for (int j = 0; j < 4; j++) aa += h[j] * es2_w[j * 4 + k];
                e[k] = aa;
            }
        }
        {
            float h[4];
            #pragma unroll
            for (int k = 0; k < 4; k++)
                h[k] = fmaxf(tj * es1_w[k] + ti * es1_w[4 + k] + es1_b[k], 0.f);
            #pragma unroll
            for (int k = 0; k < 4; k++) {
                float aa = es2_b[k];
                #pragma unroll
                for (int j = 0; j < 4; j++) aa += h[j] * es2_w[j * 4 + k];
                e[k] += aa;
            }
        }
        float y[4];
        #pragma unroll
        for (int k = 0; k < 4; k++) {
            float aa = fs1_b[k];
            #pragma unroll
            for (int j = 0; j < 4; j++) aa += e[j] * fs1_w[j * 4 + k];
            y[k] = fmaxf(aa, 0.f);
        }
        float td[4];
        #pragma unroll
        for (int k = 0; k < 4; k++) {
            float aa = fs2_b[k];
            #pragma unroll
            for (int j = 0; j < 4; j++) aa += y[j] * fs2_w[j * 4 + k];
            td[k] = aa;
        }
        #pragma unroll
        for (int o = 0; o < 8; o++) {
            float aa = 0.f;
            #pragma unroll
            for (int d = 0; d < 4; d++) aa += td[d] * en1_w[d * 8 + o];
            g_v8[tt * 8 + o] = aa;
        }
    }
}

// ---------------------------------------------------------------------------
// Helper: layers 1+2 for one survivor, two en2 columns (c0, c0+1)
// ---------------------------------------------------------------------------
__device__ __forceinline__ float2 h2_pair(
    const float4& rt, const float4* sh_v8q,
    const float* b1r, const float2* W2, const float2& b2)
{
    const int tt = (int)(__float_as_uint(rt.x) & 3u);
    const float4 v8lo = sh_v8q[tt * 2 + 0];
    const float4 v8hi = sh_v8q[tt * 2 + 1];
    const float  sm   = rt.x;

    float h1[8];
    h1[0] = fmaxf(fmaf(sm, v8lo.x, b1r[0]), 0.f);
    h1[1] = fmaxf(fmaf(sm, v8lo.y, b1r[1]), 0.f);
    h1[2] = fmaxf(fmaf(sm, v8lo.z, b1r[2]), 0.f);
    h1[3] = fmaxf(fmaf(sm, v8lo.w, b1r[3]), 0.f);
    h1[4] = fmaxf(fmaf(sm, v8hi.x, b1r[4]), 0.f);
    h1[5] = fmaxf(fmaf(sm, v8hi.y, b1r[5]), 0.f);
    h1[6] = fmaxf(fmaf(sm, v8hi.z, b1r[6]), 0.f);
    h1[7] = fmaxf(fmaf(sm, v8hi.w, b1r[7]), 0.f);

    float ha = b2.x, hb = b2.y;
    #pragma unroll
    for (int j = 0; j < 8; j++) {
        ha = fmaf(h1[j], W2[j].x, ha);
        hb = fmaf(h1[j], W2[j].y, hb);
    }
    return make_float2(fmaxf(ha, 0.f), fmaxf(hb, 0.f));
}

// ---------------------------------------------------------------------------
// Main kernel: one warp per atom; compacted survivors (tt in s_ij mantissa);
// 8 survivors per syncwarp (each lane computes h2 for 2 survivors).
// ---------------------------------------------------------------------------
__global__ __launch_bounds__(256, 3)
void descriptor_kernel(
    const int*   __restrict__ neigh,   // [S,N,M]
    const float* __restrict__ en1_b,   // [8]
    const float* __restrict__ en2_w,   // [8,16]
    const float* __restrict__ en2_b,   // [16]
    const float* __restrict__ en3_w,   // [16,32]
    const float* __restrict__ en3_b,   // [32]
    float*       __restrict__ out)     // [S,N,32,16]
{
    __shared__ float4 sh_v8q[8];            // [tt*2 + half]
    __shared__ float4 sh_rt[8][64];         // compacted survivors
    __shared__ float  sh_h2[8][2][8][16];   // [warp][parity][survivor][col]

    const int tid  = threadIdx.x;
    const int lane = tid & 31;
    const int w    = tid >> 5;

    if (tid < 32) ((float*)sh_v8q)[tid] = g_v8[tid];

    // lane g owns en3 column g; lane owns en2 columns c0, c0+1 of its quarter
    const int g  = lane;
    const int c0 = (lane & 7) * 2;
    float  W3[16], b1r[8];
    float2 W2[8];
    #pragma unroll
    for (int j = 0; j < 16; j++) W3[j] = __ldg(&en3_w[j * 32 + g]);
    #pragma unroll
    for (int j = 0; j < 8; j++)
        W2[j] = *reinterpret_cast<const float2*>(&en2_w[j * 16 + c0]);
    #pragma unroll
    for (int j = 0; j < 8; j++)  b1r[j] = __ldg(&en1_b[j]);
    const float2 b2 = *reinterpret_cast<const float2*>(&en2_b[c0]);
    const float  b3g = __ldg(&en3_b[g]);
    __syncthreads();

    const int atom = blockIdx.x * 8 + w;      // atom = s*N + n
    const int base = atom & ~4095;            // snapshot base (N = 4096)

    const float4 pi = g_pos4[atom];
    const int    ti2 = 2 * (int)pi.w;

    // -------- Phase 1: prefetch both gathers, then geometry + compaction ----
    const int2 nb2 = reinterpret_cast<const int2*>(neigh + atom * M)[lane];
    const int jj0 = (nb2.x < 0) ? 0 : nb2.x;
    const int jj1 = (nb2.y < 0) ? 0 : nb2.y;
    const float4 pj0 = g_pos4[base + jj0];
    const float4 pj1 = g_pos4[base + jj1];

    int cnt = 0;
    #pragma unroll
    for (int p = 0; p < 2; p++) {
        const int    nb = (p == 0) ? nb2.x : nb2.y;
        const float4 pj = (p == 0) ? pj0 : pj1;

        float dx = pj.x - pi.x; dx -= 20.f * rintf(dx * 0.05f);
        float dy = pj.y - pi.y; dy -= 20.f * rintf(dy * 0.05f);
        float dz = pj.z - pi.z; dz -= 20.f * rintf(dz * 0.05f);

        const float r2   = fmaf(dx, dx, fmaf(dy, dy, fmaf(dz, dz, 1e-12f)));
        const float rinv = rsqrtf(r2);
        const float r    = r2 * rinv;

        float sw;
        if (r < 2.f)      sw = 1.f;
        else if (r < 6.f) sw = fmaf(0.5f, cospif((r - 2.f) * 0.25f), 0.5f);
        else              sw = 0.f;

        const float s_ij  = (nb < 0) ? 0.f : sw * rinv;
        const float srinv = s_ij * rinv;

        const bool alive = (s_ij != 0.f);
        const unsigned bb = __ballot_sync(FULL, alive);
        if (alive) {
            // pack type-pair into 2 mantissa LSBs of s_ij (|ds/s| <= 2^-22)
            const unsigned se = (__float_as_uint(s_ij) & ~3u)
                              | (unsigned)(ti2 + (int)pj.w);
            const int pos = cnt + __popc(bb & ((1u << lane) - 1u));
            sh_rt[w][pos] = make_float4(__uint_as_float(se),
                                        dx * srinv, dy * srinv, dz * srinv);
        }
        cnt += __popc(bb);
    }
    __syncwarp();

    float A0 = 0.f, A1 = 0.f, A2 = 0.f, A3 = 0.f;
    const int qs = lane >> 3;    // survivor slot this lane serves (0..3)
    int par = 0;

    // -------- Phase 2: 8 survivors per syncwarp --------
    for (int i = 0; i < cnt; i += 8) {
        // each lane computes h2 pairs for survivors (i+qs) and (i+qs+4)
        const int sl0 = min(i + qs,     cnt - 1);
        const int sl1 = min(i + qs + 4, cnt - 1);
        const float4 rta = sh_rt[w][sl0];
        const float4 rtb = sh_rt[w][sl1];

        const float2 h2a = h2_pair(rta, sh_v8q, b1r, W2, b2);
        const float2 h2b = h2_pair(rtb, sh_v8q, b1r, W2, b2);

        *reinterpret_cast<float2*>(&sh_h2[w][par][qs][c0])     = h2a;
        *reinterpret_cast<float2*>(&sh_h2[w][par][qs + 4][c0]) = h2b;
        __syncwarp();

        // layer 3 + A accumulation, only live slots (lim is warp-uniform)
        const int lim = min(8, cnt - i);
        const float (*hh)[16] = sh_h2[w][par];
        for (int sv = 0; sv < lim; sv++) {
            const float4* hq = reinterpret_cast<const float4*>(hh[sv]);
            float G = b3g;
            #pragma unroll
            for (int q = 0; q < 4; q++) {
                const float4 hv = hq[q];
                G = fmaf(hv.x, W3[4 * q + 0], G);
                G = fmaf(hv.y, W3[4 * q + 1], G);
                G = fmaf(hv.z, W3[4 * q + 2], G);
                G = fmaf(hv.w, W3[4 * q + 3], G);
            }
            const float4 rs = sh_rt[w][i + sv];
            A0 = fmaf(G, rs.x, A0);
            A1 = fmaf(G, rs.y, A1);
            A2 = fmaf(G, rs.z, A2);
            A3 = fmaf(G, rs.w, A3);
        }
        par ^= 1;
    }

    // -------- Epilogue: D[g][k] = sum_d A[g][d]*A[k][d], k < 16 --------
    __syncwarp();
    sh_rt[w][lane] = make_float4(A0, A1, A2, A3);
    __syncwarp();

    float d[16];
    #pragma unroll
    for (int k = 0; k < 16; k++) {
        const float4 B = sh_rt[w][k];
        d[k] = fmaf(A0, B.x, fmaf(A1, B.y, fmaf(A2, B.z, A3 * B.w)));
    }

    float4* o4 = reinterpret_cast<float4*>(out + (size_t)atom * 512 + g * 16);
    o4[0] = make_float4(d[0],  d[1],  d[2],  d[3]);
    o4[1] = make_float4(d[4],  d[5],  d[6],  d[7]);
    o4[2] = make_float4(d[8],  d[9],  d[10], d[11]);
    o4[3] = make_float4(d[12], d[13], d[14], d[15]);
}

// ---------------------------------------------------------------------------
extern "C" void kernel_launch(void* const* d_in, const int* in_sizes, int n_in,
                              void* d_out, int out_size)
{
    const float* inputs      = (const float*)d_in[0];
    const int*   input_types = (const int*)  d_in[1];
    const int*   neigh_list  = (const int*)  d_in[2];
    const float* es1_w = (const float*)d_in[3];
    const float* es1_b = (const float*)d_in[4];
    const float* es2_w = (const float*)d_in[5];
    const float* es2_b = (const float*)d_in[6];
    const float* fs1_w = (const float*)d_in[7];
    const float* fs1_b = (const float*)d_in[8];
    const float* fs2_w = (const float*)d_in[9];
    const float* fs2_b = (const float*)d_in[10];
    const float* en1_w = (const float*)d_in[11];
    const float* en1_b = (const float*)d_in[12];
    const float* en2_w = (const float*)d_in[13];
    const float* en2_b = (const float*)d_in[14];
    const float* en3_w = (const float*)d_in[15];
    const float* en3_b = (const float*)d_in[16];
    float* out = (float*)d_out;

    pack_kernel<<<(SN / 4 + 255) / 256, 256>>>(inputs, input_types,
                                               es1_w, es1_b, es2_w, es2_b,
                                               fs1_w, fs1_b, fs2_w, fs2_b,
                                               en1_w);

    descriptor_kernel<<<SN / 8, 256>>>(neigh_list,
                                       en1_b, en2_w, en2_b, en3_w, en3_b,
                                       out);
}

// round 8
// speedup vs baseline: 1.0506x; 1.0506x over previous
#include <cuda_runtime.h>
#include <cstdint>

#define FULL 0xffffffffu

static constexpr int S = 8;
static constexpr int N = 4096;
static constexpr int M = 64;
static constexpr int SN = S * N;

__device__ float  g_v8[32];      // v8[tt][8] = td_table[tt] @ en1_w
__device__ float4 g_pos4[SN];    // (x, y, z, type)

// ---------------- packed f32x2 helpers (sm_103a FFMA2) ----------------
__device__ __forceinline__ void ffma2(unsigned long long& d,
                                      unsigned long long a,
                                      unsigned long long b) {
    asm("fma.rn.f32x2 %0, %1, %2, %0;" : "+l"(d) : "l"(a), "l"(b));
}
__device__ __forceinline__ unsigned long long mul2(unsigned long long a,
                                                   unsigned long long b) {
    unsigned long long d;
    asm("mul.rn.f32x2 %0, %1, %2;" : "=l"(d) : "l"(a), "l"(b));
    return d;
}
__device__ __forceinline__ unsigned long long pack2(float lo, float hi) {
    unsigned long long d;
    asm("mov.b64 %0, {%1, %2};" : "=l"(d) : "f"(lo), "f"(hi));
    return d;
}
__device__ __forceinline__ void unpack2(unsigned long long v,
                                        float& lo, float& hi) {
    asm("mov.b64 {%0, %1}, %2;" : "=f"(lo), "=f"(hi) : "l"(v));
}

// ---------------------------------------------------------------------------
// Prepass: pack positions+type into float4 (4 atoms/thread, vectorized);
// block 0 collapses species MLPs into the v8 table.
// ---------------------------------------------------------------------------
__global__ void pack_kernel(
    const float* __restrict__ pos, const int* __restrict__ types,
    const float* __restrict__ es1_w, const float* __restrict__ es1_b,
    const float* __restrict__ es2_w, const float* __restrict__ es2_b,
    const float* __restrict__ fs1_w, const float* __restrict__ fs1_b,
    const float* __restrict__ fs2_w, const float* __restrict__ fs2_b,
    const float* __restrict__ en1_w)
{
    const int idx = blockIdx.x * blockDim.x + threadIdx.x;
    if (idx < SN / 4) {
        const float4* pv = reinterpret_cast<const float4*>(pos) + idx * 3;
        const float4 a = pv[0], b = pv[1], c = pv[2];
        const int4 t = reinterpret_cast<const int4*>(types)[idx];
        float4* o = g_pos4 + idx * 4;
        o[0] = make_float4(a.x, a.y, a.z, (float)t.x);
        o[1] = make_float4(a.w, b.x, b.y, (float)t.y);
        o[2] = make_float4(b.z, b.w, c.x, (float)t.z);
        o[3] = make_float4(c.y, c.z, c.w, (float)t.w);
    }

    if (blockIdx.x == 0 && threadIdx.x < 4) {
        const int tt = threadIdx.x;
        const float ti = (float)(tt >> 1);
        const float tj = (float)(tt & 1);

        float e[4];
        {
            float h[4];
            #pragma unroll
            for (int k = 0; k < 4; k++)
                h[k] = fmaxf(ti * es1_w[k] + tj * es1_w[4 + k] + es1_b[k], 0.f);
            #pragma unroll
            for (int k = 0; k < 4; k++) {
                float aa = es2_b[k];
                #pragma unroll
                for (int j = 0; j < 4; j++) aa += h[j] * es2_w[j * 4 + k];
                e[k] = aa;
            }
        }
        {
            float h[4];
            #pragma unroll
            for (int k = 0; k < 4; k++)
                h[k] = fmaxf(tj * es1_w[k] + ti * es1_w[4 + k] + es1_b[k], 0.f);
            #pragma unroll
            for (int k = 0; k < 4; k++) {
                float aa = es2_b[k];
                #pragma unroll
                for (int j = 0; j < 4; j++) aa += h[j] * es2_w[j * 4 + k];
                e[k] += aa;
            }
        }
        float y[4];
        #pragma unroll
        for (int k = 0; k < 4; k++) {
            float aa = fs1_b[k];
            #pragma unroll
            for (int j = 0; j < 4; j++) aa += e[j] * fs1_w[j * 4 + k];
            y[k] = fmaxf(aa, 0.f);
        }
        float td[4];
        #pragma unroll
        for (int k = 0; k < 4; k++) {
            float aa = fs2_b[k];
            #pragma unroll
            for (int j = 0; j < 4; j++) aa += y[j] * fs2_w[j * 4 + k];
            td[k] = aa;
        }
        #pragma unroll
        for (int o = 0; o < 8; o++) {
            float aa = 0.f;
            #pragma unroll
            for (int d = 0; d < 4; d++) aa += td[d] * en1_w[d * 8 + o];
            g_v8[tt * 8 + o] = aa;
        }
    }
}

// ---------------------------------------------------------------------------
// Main kernel: one warp per atom; compacted survivors (tt in s_ij mantissa);
// 4 survivors per syncwarp with uniform live limit; f32x2-packed layer-3,
// A-accumulation, and Gram epilogue.
// ---------------------------------------------------------------------------
__global__ __launch_bounds__(256, 3)
void descriptor_kernel(
    const int*   __restrict__ neigh,   // [S,N,M]
    const float* __restrict__ en1_b,   // [8]
    const float* __restrict__ en2_w,   // [8,16]
    const float* __restrict__ en2_b,   // [16]
    const float* __restrict__ en3_w,   // [16,32]
    const float* __restrict__ en3_b,   // [32]
    float*       __restrict__ out)     // [S,N,32,16]
{
    __shared__ float4 sh_v8q[8];            // [tt*2 + half]
    __shared__ float4 sh_rt[8][64];         // compacted survivors / shT reuse
    __shared__ float  sh_h2[8][2][4][16];   // [warp][parity][survivor][col]

    const int tid  = threadIdx.x;
    const int lane = tid & 31;
    const int w    = tid >> 5;

    if (tid < 32) ((float*)sh_v8q)[tid] = g_v8[tid];

    // lane g owns en3 column g (packed in col-pairs); en2 columns c0, c0+1
    const int g  = lane;
    const int c0 = (lane & 7) * 2;
    float2 W3f[8];             // (W3[2q], W3[2q+1]) for column g
    float2 W2[8];
    float  b1r[8];
    #pragma unroll
    for (int q = 0; q < 8; q++) {
        W3f[q].x = __ldg(&en3_w[(2 * q)     * 32 + g]);
        W3f[q].y = __ldg(&en3_w[(2 * q + 1) * 32 + g]);
    }
    #pragma unroll
    for (int j = 0; j < 8; j++)
        W2[j] = *reinterpret_cast<const float2*>(&en2_w[j * 16 + c0]);
    #pragma unroll
    for (int j = 0; j < 8; j++)  b1r[j] = __ldg(&en1_b[j]);
    const float2 b2 = *reinterpret_cast<const float2*>(&en2_b[c0]);
    const unsigned long long b3g2 = pack2(__ldg(&en3_b[g]), 0.f);
    __syncthreads();

    const int atom = blockIdx.x * 8 + w;      // atom = s*N + n
    const int base = atom & ~4095;            // snapshot base (N = 4096)

    const float4 pi = g_pos4[atom];
    const int    ti2 = 2 * (int)pi.w;

    // -------- Phase 1: prefetch both gathers, then geometry + compaction ----
    const int2 nb2 = reinterpret_cast<const int2*>(neigh + atom * M)[lane];
    const int jj0 = (nb2.x < 0) ? 0 : nb2.x;
    const int jj1 = (nb2.y < 0) ? 0 : nb2.y;
    const float4 pj0 = g_pos4[base + jj0];
    const float4 pj1 = g_pos4[base + jj1];

    int cnt = 0;
    #pragma unroll
    for (int p = 0; p < 2; p++) {
        const int    nb = (p == 0) ? nb2.x : nb2.y;
        const float4 pj = (p == 0) ? pj0 : pj1;

        float dx = pj.x - pi.x; dx -= 20.f * rintf(dx * 0.05f);
        float dy = pj.y - pi.y; dy -= 20.f * rintf(dy * 0.05f);
        float dz = pj.z - pi.z; dz -= 20.f * rintf(dz * 0.05f);

        const float r2   = fmaf(dx, dx, fmaf(dy, dy, fmaf(dz, dz, 1e-12f)));
        const float rinv = rsqrtf(r2);
        const float r    = r2 * rinv;

        float sw;
        if (r < 2.f)      sw = 1.f;
        else if (r < 6.f) sw = fmaf(0.5f, cospif((r - 2.f) * 0.25f), 0.5f);
        else              sw = 0.f;

        const float s_ij  = (nb < 0) ? 0.f : sw * rinv;
        const float srinv = s_ij * rinv;

        const bool alive = (s_ij != 0.f);
        const unsigned bb = __ballot_sync(FULL, alive);
        if (alive) {
            // pack type-pair into 2 mantissa LSBs of s_ij (|ds/s| <= 2^-22)
            const unsigned se = (__float_as_uint(s_ij) & ~3u)
                              | (unsigned)(ti2 + (int)pj.w);
            const int pos = cnt + __popc(bb & ((1u << lane) - 1u));
            sh_rt[w][pos] = make_float4(__uint_as_float(se),
                                        dx * srinv, dy * srinv, dz * srinv);
        }
        cnt += __popc(bb);
    }
    __syncwarp();

    unsigned long long A01 = 0ull, A23 = 0ull;   // (A0,A1), (A2,A3) packed
    const int qs = lane >> 3;    // survivor slot this lane serves (0..3)
    int par = 0;

    // -------- Phase 2: 4 survivors per iteration, uniform live limit --------
    for (int i = 0; i < cnt; i += 4) {
        const int    sl = min(i + qs, cnt - 1);
        const float4 rt = sh_rt[w][sl];
        const int    tt = (int)(__float_as_uint(rt.x) & 3u);
        const float4 v8lo = sh_v8q[tt * 2 + 0];
        const float4 v8hi = sh_v8q[tt * 2 + 1];
        const float  sm   = rt.x;

        // layer 1 (8 outputs shared by this lane's 2 columns)
        float h1[8];
        h1[0] = fmaxf(fmaf(sm, v8lo.x, b1r[0]), 0.f);
        h1[1] = fmaxf(fmaf(sm, v8lo.y, b1r[1]), 0.f);
        h1[2] = fmaxf(fmaf(sm, v8lo.z, b1r[2]), 0.f);
        h1[3] = fmaxf(fmaf(sm, v8lo.w, b1r[3]), 0.f);
        h1[4] = fmaxf(fmaf(sm, v8hi.x, b1r[4]), 0.f);
        h1[5] = fmaxf(fmaf(sm, v8hi.y, b1r[5]), 0.f);
        h1[6] = fmaxf(fmaf(sm, v8hi.z, b1r[6]), 0.f);
        h1[7] = fmaxf(fmaf(sm, v8hi.w, b1r[7]), 0.f);

        // layer 2: two columns (c0, c0+1)
        float ha = b2.x, hb = b2.y;
        #pragma unroll
        for (int j = 0; j < 8; j++) {
            ha = fmaf(h1[j], W2[j].x, ha);
            hb = fmaf(h1[j], W2[j].y, hb);
        }
        ha = fmaxf(ha, 0.f);
        hb = fmaxf(hb, 0.f);

        *reinterpret_cast<float2*>(&sh_h2[w][par][qs][c0]) = make_float2(ha, hb);
        __syncwarp();

        // layer 3 + A accumulation, f32x2-packed, only live slots
        const int lim = min(4, cnt - i);
        for (int sv = 0; sv < lim; sv++) {
            const ulonglong2* hq =
                reinterpret_cast<const ulonglong2*>(sh_h2[w][par][sv]);
            const ulonglong2 hA = hq[0];
            const ulonglong2 hB = hq[1];
            unsigned long long acc = b3g2;
            ffma2(acc, hA.x, *reinterpret_cast<const unsigned long long*>(&W3f[0]));
            ffma2(acc, hA.y, *reinterpret_cast<const unsigned long long*>(&W3f[1]));
            ffma2(acc, hB.x, *reinterpret_cast<const unsigned long long*>(&W3f[2]));
            ffma2(acc, hB.y, *reinterpret_cast<const unsigned long long*>(&W3f[3]));
            const ulonglong2 hC = hq[2];
            const ulonglong2 hD = hq[3];
            ffma2(acc, hC.x, *reinterpret_cast<const unsigned long long*>(&W3f[4]));
            ffma2(acc, hC.y, *reinterpret_cast<const unsigned long long*>(&W3f[5]));
            ffma2(acc, hD.x, *reinterpret_cast<const unsigned long long*>(&W3f[6]));
            ffma2(acc, hD.y, *reinterpret_cast<const unsigned long long*>(&W3f[7]));
            float glo, ghi;
            unpack2(acc, glo, ghi);
            const float G = glo + ghi;

            const unsigned long long G2 = pack2(G, G);
            const ulonglong2 rt2 =
                *reinterpret_cast<const ulonglong2*>(&sh_rt[w][i + sv]);
            ffma2(A01, G2, rt2.x);
            ffma2(A23, G2, rt2.y);
        }
        par ^= 1;
    }

    // -------- Epilogue: D[g][k] = sum_d A[g][d]*A[k][d], k < 16 ------------
    float a0, a1, a2, a3;
    unpack2(A01, a0, a1);
    unpack2(A23, a2, a3);

    // transposed stash: shT[d][k] (reuse sh_rt storage: 4*32 floats)
    float* shT = reinterpret_cast<float*>(&sh_rt[w][0]);
    __syncwarp();
    shT[0 * 32 + lane] = a0;
    shT[1 * 32 + lane] = a1;
    shT[2 * 32 + lane] = a2;
    shT[3 * 32 + lane] = a3;
    __syncwarp();

    const unsigned long long d0 = pack2(a0, a0);
    const unsigned long long d1 = pack2(a1, a1);
    const unsigned long long d2 = pack2(a2, a2);
    const unsigned long long d3 = pack2(a3, a3);

    float4* o4 = reinterpret_cast<float4*>(out + (size_t)atom * 512 + g * 16);
    #pragma unroll
    for (int kg = 0; kg < 4; kg++) {
        const int k0 = kg * 4;
        const ulonglong2 r0 = *reinterpret_cast<const ulonglong2*>(&shT[0 * 32 + k0]);
        const ulonglong2 r1 = *reinterpret_cast<const ulonglong2*>(&shT[1 * 32 + k0]);
        const ulonglong2 r2 = *reinterpret_cast<const ulonglong2*>(&shT[2 * 32 + k0]);
        const ulonglong2 r3 = *reinterpret_cast<const ulonglong2*>(&shT[3 * 32 + k0]);

        unsigned long long accA = mul2(d0, r0.x);   // (d[k0], d[k0+1])
        unsigned long long accB = mul2(d0, r0.y);   // (d[k0+2], d[k0+3])
        ffma2(accA, d1, r1.x);  ffma2(accB, d1, r1.y);
        ffma2(accA, d2, r2.x);  ffma2(accB, d2, r2.y);
        ffma2(accA, d3, r3.x);  ffma2(accB, d3, r3.y);

        float4 res;
        unpack2(accA, res.x, res.y);
        unpack2(accB, res.z, res.w);
        o4[kg] = res;
    }
}

// ---------------------------------------------------------------------------
extern "C" void kernel_launch(void* const* d_in, const int* in_sizes, int n_in,
                              void* d_out, int out_size)
{
    const float* inputs      = (const float*)d_in[0];
    const int*   input_types = (const int*)  d_in[1];
    const int*   neigh_list  = (const int*)  d_in[2];
    const float* es1_w = (const float*)d_in[3];
    const float* es1_b = (const float*)d_in[4];
    const float* es2_w = (const float*)d_in[5];
    const float* es2_b = (const float*)d_in[6];
    const float* fs1_w = (const float*)d_in[7];
    const float* fs1_b = (const float*)d_in[8];
    const float* fs2_w = (const float*)d_in[9];
    const float* fs2_b = (const float*)d_in[10];
    const float* en1_w = (const float*)d_in[11];
    const float* en1_b = (const float*)d_in[12];
    const float* en2_w = (const float*)d_in[13];
    const float* en2_b = (const float*)d_in[14];
    const float* en3_w = (const float*)d_in[15];
    const float* en3_b = (const float*)d_in[16];
    float* out = (float*)d_out;

    pack_kernel<<<(SN / 4 + 255) / 256, 256>>>(inputs, input_types,
                                               es1_w, es1_b, es2_w, es2_b,
                                               fs1_w, fs1_b, fs2_w, fs2_b,
                                               en1_w);

    descriptor_kernel<<<SN / 8, 256>>>(neigh_list,
                                       en1_b, en2_w, en2_b, en3_w, en3_b,
                                       out);
}

// round 9
// speedup vs baseline: 1.0513x; 1.0007x over previous
#include <cuda_runtime.h>
#include <cstdint>

#define FULL 0xffffffffu

static constexpr int S = 8;
static constexpr int N = 4096;
static constexpr int M = 64;
static constexpr int SN = S * N;
static constexpr int APW = 4;                 // atoms per warp

__device__ float  g_v8[32];      // v8[tt][8] = td_table[tt] @ en1_w
__device__ float4 g_pos4[SN];    // (x, y, z, type)

// ---------------- packed f32x2 helpers (sm_103a FFMA2) ----------------
__device__ __forceinline__ void ffma2(unsigned long long& d,
                                      unsigned long long a,
                                      unsigned long long b) {
    asm("fma.rn.f32x2 %0, %1, %2, %0;" : "+l"(d) : "l"(a), "l"(b));
}
__device__ __forceinline__ unsigned long long mul2(unsigned long long a,
                                                   unsigned long long b) {
    unsigned long long d;
    asm("mul.rn.f32x2 %0, %1, %2;" : "=l"(d) : "l"(a), "l"(b));
    return d;
}
__device__ __forceinline__ unsigned long long pack2(float lo, float hi) {
    unsigned long long d;
    asm("mov.b64 %0, {%1, %2};" : "=l"(d) : "f"(lo), "f"(hi));
    return d;
}
__device__ __forceinline__ void unpack2(unsigned long long v,
                                        float& lo, float& hi) {
    asm("mov.b64 {%0, %1}, %2;" : "=f"(lo), "=f"(hi) : "l"(v));
}

// ---------------------------------------------------------------------------
// Prepass: pack positions+type into float4 (4 atoms/thread, vectorized);
// block 0 collapses species MLPs into the v8 table.
// ---------------------------------------------------------------------------
__global__ void pack_kernel(
    const float* __restrict__ pos, const int* __restrict__ types,
    const float* __restrict__ es1_w, const float* __restrict__ es1_b,
    const float* __restrict__ es2_w, const float* __restrict__ es2_b,
    const float* __restrict__ fs1_w, const float* __restrict__ fs1_b,
    const float* __restrict__ fs2_w, const float* __restrict__ fs2_b,
    const float* __restrict__ en1_w)
{
    const int idx = blockIdx.x * blockDim.x + threadIdx.x;
    if (idx < SN / 4) {
        const float4* pv = reinterpret_cast<const float4*>(pos) + idx * 3;
        const float4 a = pv[0], b = pv[1], c = pv[2];
        const int4 t = reinterpret_cast<const int4*>(types)[idx];
        float4* o = g_pos4 + idx * 4;
        o[0] = make_float4(a.x, a.y, a.z, (float)t.x);
        o[1] = make_float4(a.w, b.x, b.y, (float)t.y);
        o[2] = make_float4(b.z, b.w, c.x, (float)t.z);
        o[3] = make_float4(c.y, c.z, c.w, (float)t.w);
    }

    if (blockIdx.x == 0 && threadIdx.x < 4) {
        const int tt = threadIdx.x;
        const float ti = (float)(tt >> 1);
        const float tj = (float)(tt & 1);

        float e[4];
        {
            float h[4];
            #pragma unroll
            for (int k = 0; k < 4; k++)
                h[k] = fmaxf(ti * es1_w[k] + tj * es1_w[4 + k] + es1_b[k], 0.f);
            #pragma unroll
            for (int k = 0; k < 4; k++) {
                float aa = es2_b[k];
                #pragma unroll
                for (int j = 0; j < 4; j++) aa += h[j] * es2_w[j * 4 + k];
                e[k] = aa;
            }
        }
        {
            float h[4];
            #pragma unroll
            for (int k = 0; k < 4; k++)
                h[k] = fmaxf(tj * es1_w[k] + ti * es1_w[4 + k] + es1_b[k], 0.f);
            #pragma unroll
            for (int k = 0; k < 4; k++) {
                float aa = es2_b[k];
                #pragma unroll
                for (int j = 0; j < 4; j++) aa += h[j] * es2_w[j * 4 + k];
                e[k] += aa;
            }
        }
        float y[4];
        #pragma unroll
        for (int k = 0; k < 4; k++) {
            float aa = fs1_b[k];
            #pragma unroll
            for (int j = 0; j < 4; j++) aa += e[j] * fs1_w[j * 4 + k];
            y[k] = fmaxf(aa, 0.f);
        }
        float td[4];
        #pragma unroll
        for (int k = 0; k < 4; k++) {
            float aa = fs2_b[k];
            #pragma unroll
            for (int j = 0; j < 4; j++) aa += y[j] * fs2_w[j * 4 + k];
            td[k] = aa;
        }
        #pragma unroll
        for (int o = 0; o < 8; o++) {
            float aa = 0.f;
            #pragma unroll
            for (int d = 0; d < 4; d++) aa += td[d] * en1_w[d * 8 + o];
            g_v8[tt * 8 + o] = aa;
        }
    }
}

// ---------------------------------------------------------------------------
// Helper: layers 1+2 for one survivor, two en2 columns (c0, c0+1)
// ---------------------------------------------------------------------------
__device__ __forceinline__ float2 h2_pair(
    const float4& rt, const float4* sh_v8q,
    const float* b1r, const float2* W2, const float2& b2)
{
    const int tt = (int)(__float_as_uint(rt.x) & 3u);
    const float4 v8lo = sh_v8q[tt * 2 + 0];
    const float4 v8hi = sh_v8q[tt * 2 + 1];
    const float  sm   = rt.x;

    float h1[8];
    h1[0] = fmaxf(fmaf(sm, v8lo.x, b1r[0]), 0.f);
    h1[1] = fmaxf(fmaf(sm, v8lo.y, b1r[1]), 0.f);
    h1[2] = fmaxf(fmaf(sm, v8lo.z, b1r[2]), 0.f);
    h1[3] = fmaxf(fmaf(sm, v8lo.w, b1r[3]), 0.f);
    h1[4] = fmaxf(fmaf(sm, v8hi.x, b1r[4]), 0.f);
    h1[5] = fmaxf(fmaf(sm, v8hi.y, b1r[5]), 0.f);
    h1[6] = fmaxf(fmaf(sm, v8hi.z, b1r[6]), 0.f);
    h1[7] = fmaxf(fmaf(sm, v8hi.w, b1r[7]), 0.f);

    float ha = b2.x, hb = b2.y;
    #pragma unroll
    for (int j = 0; j < 8; j++) {
        ha = fmaf(h1[j], W2[j].x, ha);
        hb = fmaf(h1[j], W2[j].y, hb);
    }
    return make_float2(fmaxf(ha, 0.f), fmaxf(hb, 0.f));
}

// ---------------------------------------------------------------------------
// Main kernel: 4 atoms per warp (weights amortized); compacted survivors
// (tt in s_ij mantissa); adaptive 4/8-wide phase 2; f32x2-packed math.
// ---------------------------------------------------------------------------
__global__ __launch_bounds__(256, 3)
void descriptor_kernel(
    const int*   __restrict__ neigh,   // [S,N,M]
    const float* __restrict__ en1_b,   // [8]
    const float* __restrict__ en2_w,   // [8,16]
    const float* __restrict__ en2_b,   // [16]
    const float* __restrict__ en3_w,   // [16,32]
    const float* __restrict__ en3_b,   // [32]
    float*       __restrict__ out)     // [S,N,32,16]
{
    __shared__ float4 sh_v8q[8];            // [tt*2 + half]
    __shared__ float4 sh_rt[8][64];         // compacted survivors / shT reuse
    __shared__ float  sh_h2[8][2][8][16];   // [warp][parity][survivor][col]

    const int tid  = threadIdx.x;
    const int lane = tid & 31;
    const int w    = tid >> 5;

    if (tid < 32) ((float*)sh_v8q)[tid] = g_v8[tid];

    // lane g owns en3 column g (packed col-pairs); en2 columns c0, c0+1
    const int g  = lane;
    const int c0 = (lane & 7) * 2;
    float2 W3f[8];             // (W3[2q], W3[2q+1]) for column g
    float2 W2[8];
    float  b1r[8];
    #pragma unroll
    for (int q = 0; q < 8; q++) {
        W3f[q].x = __ldg(&en3_w[(2 * q)     * 32 + g]);
        W3f[q].y = __ldg(&en3_w[(2 * q + 1) * 32 + g]);
    }
    #pragma unroll
    for (int j = 0; j < 8; j++)
        W2[j] = *reinterpret_cast<const float2*>(&en2_w[j * 16 + c0]);
    #pragma unroll
    for (int j = 0; j < 8; j++)  b1r[j] = __ldg(&en1_b[j]);
    const float2 b2 = *reinterpret_cast<const float2*>(&en2_b[c0]);
    const unsigned long long b3g2 = pack2(__ldg(&en3_b[g]), 0.f);
    __syncthreads();

    const int warpBase = (blockIdx.x * 8 + w) * APW;
    const int qs = lane >> 3;    // survivor slot this lane serves (0..3)
    int par = 0;

    for (int a = 0; a < APW; a++) {
        const int atom = warpBase + a;            // atom = s*N + n
        const int base = atom & ~4095;            // snapshot base (N = 4096)

        const float4 pi = g_pos4[atom];
        const int    ti2 = 2 * (int)pi.w;

        // ---- Phase 1: prefetch gathers, then geometry + compaction ----
        const int2 nb2 = reinterpret_cast<const int2*>(neigh + atom * M)[lane];
        const int jj0 = (nb2.x < 0) ? 0 : nb2.x;
        const int jj1 = (nb2.y < 0) ? 0 : nb2.y;
        const float4 pj0 = g_pos4[base + jj0];
        const float4 pj1 = g_pos4[base + jj1];

        __syncwarp();   // previous atom's epilogue reads of sh_rt done

        int cnt = 0;
        #pragma unroll
        for (int p = 0; p < 2; p++) {
            const int    nb = (p == 0) ? nb2.x : nb2.y;
            const float4 pj = (p == 0) ? pj0 : pj1;

            float dx = pj.x - pi.x; dx -= 20.f * rintf(dx * 0.05f);
            float dy = pj.y - pi.y; dy -= 20.f * rintf(dy * 0.05f);
            float dz = pj.z - pi.z; dz -= 20.f * rintf(dz * 0.05f);

            const float r2   = fmaf(dx, dx, fmaf(dy, dy, fmaf(dz, dz, 1e-12f)));
            const float rinv = rsqrtf(r2);
            const float r    = r2 * rinv;

            float sw;
            if (r < 2.f)      sw = 1.f;
            else if (r < 6.f) sw = fmaf(0.5f, cospif((r - 2.f) * 0.25f), 0.5f);
            else              sw = 0.f;

            const float s_ij  = (nb < 0) ? 0.f : sw * rinv;
            const float srinv = s_ij * rinv;

            const bool alive = (s_ij != 0.f);
            const unsigned bb = __ballot_sync(FULL, alive);
            if (alive) {
                // type-pair in 2 mantissa LSBs of s_ij (|ds/s| <= 2^-22)
                const unsigned se = (__float_as_uint(s_ij) & ~3u)
                                  | (unsigned)(ti2 + (int)pj.w);
                const int pos = cnt + __popc(bb & ((1u << lane) - 1u));
                sh_rt[w][pos] = make_float4(__uint_as_float(se),
                                            dx * srinv, dy * srinv, dz * srinv);
            }
            cnt += __popc(bb);
        }
        __syncwarp();

        unsigned long long A01 = 0ull, A23 = 0ull;   // (A0,A1),(A2,A3)

        // ---- Phase 2: adaptive 4/8 survivors per syncwarp ----
        for (int i = 0; i < cnt; i += 8) {
            const float4 rta = sh_rt[w][min(i + qs, cnt - 1)];
            const float2 h2a = h2_pair(rta, sh_v8q, b1r, W2, b2);
            *reinterpret_cast<float2*>(&sh_h2[w][par][qs][c0]) = h2a;
            if (i + 4 < cnt) {   // warp-uniform: fill the upper 4 slots
                const float4 rtb = sh_rt[w][min(i + qs + 4, cnt - 1)];
                const float2 h2b = h2_pair(rtb, sh_v8q, b1r, W2, b2);
                *reinterpret_cast<float2*>(&sh_h2[w][par][qs + 4][c0]) = h2b;
            }
            __syncwarp();

            const int lim = min(8, cnt - i);
            const float (*hh)[16] = sh_h2[w][par];
            for (int sv = 0; sv < lim; sv++) {
                const ulonglong2* hq =
                    reinterpret_cast<const ulonglong2*>(hh[sv]);
                const ulonglong2 hA = hq[0];
                const ulonglong2 hB = hq[1];
                unsigned long long acc = b3g2;
                ffma2(acc, hA.x, *reinterpret_cast<const unsigned long long*>(&W3f[0]));
                ffma2(acc, hA.y, *reinterpret_cast<const unsigned long long*>(&W3f[1]));
                ffma2(acc, hB.x, *reinterpret_cast<const unsigned long long*>(&W3f[2]));
                ffma2(acc, hB.y, *reinterpret_cast<const unsigned long long*>(&W3f[3]));
                const ulonglong2 hC = hq[2];
                const ulonglong2 hD = hq[3];
                ffma2(acc, hC.x, *reinterpret_cast<const unsigned long long*>(&W3f[4]));
                ffma2(acc, hC.y, *reinterpret_cast<const unsigned long long*>(&W3f[5]));
                ffma2(acc, hD.x, *reinterpret_cast<const unsigned long long*>(&W3f[6]));
                ffma2(acc, hD.y, *reinterpret_cast<const unsigned long long*>(&W3f[7]));
                float glo, ghi;
                unpack2(acc, glo, ghi);
                const float G = glo + ghi;

                const unsigned long long G2 = pack2(G, G);
                const ulonglong2 rt2 =
                    *reinterpret_cast<const ulonglong2*>(&sh_rt[w][i + sv]);
                ffma2(A01, G2, rt2.x);
                ffma2(A23, G2, rt2.y);
            }
            par ^= 1;
        }

        // ---- Epilogue: D[g][k] = sum_d A[g][d]*A[k][d], k < 16 ----
        float a0, a1, a2, a3;
        unpack2(A01, a0, a1);
        unpack2(A23, a2, a3);

        float* shT = reinterpret_cast<float*>(&sh_rt[w][0]);
        __syncwarp();   // all lanes done reading sh_rt survivors
        shT[0 * 32 + lane] = a0;
        shT[1 * 32 + lane] = a1;
        shT[2 * 32 + lane] = a2;
        shT[3 * 32 + lane] = a3;
        __syncwarp();

        const unsigned long long d0 = pack2(a0, a0);
        const unsigned long long d1 = pack2(a1, a1);
        const unsigned long long d2 = pack2(a2, a2);
        const unsigned long long d3 = pack2(a3, a3);

        float4* o4 = reinterpret_cast<float4*>(out + (size_t)atom * 512 + g * 16);
        #pragma unroll
        for (int kg = 0; kg < 4; kg++) {
            const int k0 = kg * 4;
            const ulonglong2 r0 = *reinterpret_cast<const ulonglong2*>(&shT[0 * 32 + k0]);
            const ulonglong2 r1 = *reinterpret_cast<const ulonglong2*>(&shT[1 * 32 + k0]);
            const ulonglong2 r2 = *reinterpret_cast<const ulonglong2*>(&shT[2 * 32 + k0]);
            const ulonglong2 r3 = *reinterpret_cast<const ulonglong2*>(&shT[3 * 32 + k0]);

            unsigned long long accA = mul2(d0, r0.x);   // (d[k0], d[k0+1])
            unsigned long long accB = mul2(d0, r0.y);   // (d[k0+2], d[k0+3])
            ffma2(accA, d1, r1.x);  ffma2(accB, d1, r1.y);
            ffma2(accA, d2, r2.x);  ffma2(accB, d2, r2.y);
            ffma2(accA, d3, r3.x);  ffma2(accB, d3, r3.y);

            float4 res;
            unpack2(accA, res.x, res.y);
            unpack2(accB, res.z, res.w);
            o4[kg] = res;
        }
    }
}

// ---------------------------------------------------------------------------
extern "C" void kernel_launch(void* const* d_in, const int* in_sizes, int n_in,
                              void* d_out, int out_size)
{
    const float* inputs      = (const float*)d_in[0];
    const int*   input_types = (const int*)  d_in[1];
    const int*   neigh_list  = (const int*)  d_in[2];
    const float* es1_w = (const float*)d_in[3];
    const float* es1_b = (const float*)d_in[4];
    const float* es2_w = (const float*)d_in[5];
    const float* es2_b = (const float*)d_in[6];
    const float* fs1_w = (const float*)d_in[7];
    const float* fs1_b = (const float*)d_in[8];
    const float* fs2_w = (const float*)d_in[9];
    const float* fs2_b = (const float*)d_in[10];
    const float* en1_w = (const float*)d_in[11];
    const float* en1_b = (const float*)d_in[12];
    const float* en2_w = (const float*)d_in[13];
    const float* en2_b = (const float*)d_in[14];
    const float* en3_w = (const float*)d_in[15];
    const float* en3_b = (const float*)d_in[16];
    float* out = (float*)d_out;

    pack_kernel<<<(SN / 4 + 255) / 256, 256>>>(inputs, input_types,
                                               es1_w, es1_b, es2_w, es2_b,
                                               fs1_w, fs1_b, fs2_w, fs2_b,
                                               en1_w);

    descriptor_kernel<<<SN / (8 * APW), 256>>>(neigh_list,
                                               en1_b, en2_w, en2_b,
                                               en3_w, en3_b, out);
}